// round 13
// baseline (speedup 1.0000x reference)
#include <cuda_runtime.h>
#include <math_constants.h>

#define N 8192
#define D 512
#define ROWS 16      // rows per LSE block
#define BOOT 12      // bootstrap iterations using two-pass kernel
#define NBLK (N / ROWS)   // 512 row-band blocks

// quantization: C stored as uint16, value = q / QSCALE, QSCALE = 1600 (max 40.96)
#define QSCALE    1600.0f
#define KC        28.85390081777927f          // 1/(eps*ln2)
#define QK        (KC / QSCALE)
#define EPSLN2    0.034657359027997264f       // eps*ln2
#define EPSLOGN   0.4505456673639644f         // eps*ln(8192)

// ---------------- device scratch (no allocations allowed) ----------------
__device__ __align__(256) unsigned short d_Cxy[67108864];   // 128MB each
__device__ __align__(256) unsigned short d_Cyx[67108864];   // used in bootstrap only
__device__ __align__(256) unsigned short d_Cxx[67108864];
__device__ __align__(256) unsigned short d_Cyy[67108864];
__device__ __align__(256) float d_colpart[NBLK][N];         // 16MB column partials
__device__ __align__(256) float d_sx[N];
__device__ __align__(256) float d_sy[N];
__device__ __align__(256) float d_vecs[2][4][N];   // ping-pong f,g,p,q
__device__ __align__(256) float d_evec[4][N];      // f_e, g_e, p_e, q_e
__device__ __align__(256) float d_ref[4][N];       // last row-lse2 per matrix (base-2 units)

// ---------------- row squared-norms ----------------
__global__ void rownorm_kernel(const float* __restrict__ X, const float* __restrict__ PZ) {
    const float* src = (blockIdx.y == 0) ? PZ : X;    // y=0: xs=prior_z -> sx
    float* dst = (blockIdx.y == 0) ? d_sx : d_sy;
    int row = blockIdx.x * 8 + (threadIdx.x >> 5);
    int lane = threadIdx.x & 31;
    const float4* xr = (const float4*)(src + (size_t)row * D);
    float s = 0.f;
    #pragma unroll
    for (int t = lane; t < D / 4; t += 32) {
        float4 v = xr[t];
        s += v.x * v.x + v.y * v.y + v.z * v.z + v.w * v.w;
    }
    #pragma unroll
    for (int o = 16; o; o >>= 1) s += __shfl_down_sync(0xffffffffu, s, o);
    if (lane == 0) dst[row] = s;
}

__global__ void init_kernel() {
    int i = blockIdx.x * blockDim.x + threadIdx.x;
    if (i < 2 * 4 * N) ((float*)d_vecs)[i] = 0.f;
}

// ---------------- fused GEMM + distance + uint16 quantize ----------------
__global__ __launch_bounds__(256, 2) void gemm_dist_kernel(
    const float* __restrict__ X, const float* __restrict__ PZ, int which)
{
    const float *A, *B, *sA, *sB;
    unsigned short *C, *Cm;
    bool sym;
    if (which == 0)      { A = PZ; B = X;  sA = d_sx; sB = d_sy; C = d_Cxy; Cm = d_Cyx; sym = false; }
    else if (which == 1) { A = PZ; B = PZ; sA = d_sx; sB = d_sx; C = d_Cxx; Cm = d_Cxx; sym = true;  }
    else                 { A = X;  B = X;  sA = d_sy; sB = d_sy; C = d_Cyy; Cm = d_Cyy; sym = true;  }

    int bx = blockIdx.x, by = blockIdx.y;
    if (sym && by > bx) return;   // triangular tiles only; mirror via transpose store

    __shared__ float As[16][132];
    __shared__ float Bs[16][132];
    __shared__ unsigned int ts[128][65];   // packed uint16 pairs, pad->conflict-free cols

    int tid = threadIdx.x;
    int ty = tid >> 4, tx = tid & 15;
    int trow = ty * 8, tcol = tx * 8;

    float acc[8][8];
    #pragma unroll
    for (int i = 0; i < 8; i++)
        #pragma unroll
        for (int j = 0; j < 8; j++) acc[i][j] = 0.f;

    const float* Ab = A + (size_t)by * 128 * D;
    const float* Bb = B + (size_t)bx * 128 * D;

    for (int k0 = 0; k0 < D; k0 += 16) {
        #pragma unroll
        for (int l = 0; l < 2; l++) {
            int idx = tid + l * 256;       // 0..511
            int r = idx >> 2;              // 0..127
            int c = (idx & 3) << 2;        // 0,4,8,12
            float4 av = *(const float4*)(Ab + (size_t)r * D + k0 + c);
            As[c + 0][r] = av.x; As[c + 1][r] = av.y; As[c + 2][r] = av.z; As[c + 3][r] = av.w;
            float4 bv = *(const float4*)(Bb + (size_t)r * D + k0 + c);
            Bs[c + 0][r] = bv.x; Bs[c + 1][r] = bv.y; Bs[c + 2][r] = bv.z; Bs[c + 3][r] = bv.w;
        }
        __syncthreads();
        #pragma unroll
        for (int kk = 0; kk < 16; kk++) {
            float ar[8], br[8];
            #pragma unroll
            for (int i = 0; i < 8; i++) ar[i] = As[kk][trow + i];
            #pragma unroll
            for (int j = 0; j < 8; j++) br[j] = Bs[kk][tcol + j];
            #pragma unroll
            for (int i = 0; i < 8; i++)
                #pragma unroll
                for (int j = 0; j < 8; j++)
                    acc[i][j] = fmaf(ar[i], br[j], acc[i][j]);
        }
        __syncthreads();
    }

    int gr0 = by * 128, gc0 = bx * 128;
    float sa[8], sb[8];
    #pragma unroll
    for (int i = 0; i < 8; i++) sa[i] = sA[gr0 + trow + i];
    #pragma unroll
    for (int j = 0; j < 8; j++) sb[j] = sB[gc0 + tcol + j];

    #pragma unroll
    for (int i = 0; i < 8; i++) {
        #pragma unroll
        for (int j = 0; j < 8; j += 2) {
            float sq0 = sa[i] + sb[j]     - 2.f * acc[i][j];
            float sq1 = sa[i] + sb[j + 1] - 2.f * acc[i][j + 1];
            float d0 = sqrtf(fmaxf(sq0, 1e-12f));
            float d1 = sqrtf(fmaxf(sq1, 1e-12f));
            unsigned int q0 = min(65535u, __float2uint_rn(d0 * QSCALE));
            unsigned int q1 = min(65535u, __float2uint_rn(d1 * QSCALE));
            ts[trow + i][(tcol + j) >> 1] = q0 | (q1 << 16);
        }
    }
    __syncthreads();

    for (int idx = tid; idx < 128 * 16; idx += 256) {
        int r = idx >> 4, seg = idx & 15;
        uint4 w;
        w.x = ts[r][seg * 4 + 0];
        w.y = ts[r][seg * 4 + 1];
        w.z = ts[r][seg * 4 + 2];
        w.w = ts[r][seg * 4 + 3];
        *(uint4*)&C[(size_t)(gr0 + r) * N + gc0 + seg * 8] = w;
    }
    for (int idx = tid; idx < 128 * 16; idx += 256) {
        int c = idx >> 4, seg = idx & 15;
        uint4 w;
        unsigned int sh = (c & 1) * 16;
        #pragma unroll
        for (int k = 0; k < 4; k++) {
            int r = seg * 8 + k * 2;
            unsigned int lo = (ts[r][c >> 1] >> sh) & 0xFFFFu;
            unsigned int hi = (ts[r + 1][c >> 1] >> sh) & 0xFFFFu;
            ((unsigned int*)&w)[k] = lo | (hi << 16);
        }
        *(uint4*)&Cm[(size_t)(gc0 + c) * N + gr0 + seg * 8] = w;
    }
}

// shared operand-selection helper for LSE kernels
#define LSE_SELECT() \
    const float* base_r = &d_vecs[parity][0][0]; \
    float* base_w = &d_vecs[parity ^ 1][0][0]; \
    const unsigned short* Cq; const float* vin; const float* vold; float* vout; \
    if (which == 0)      { Cq = d_Cxy; vin = base_r + N;     vold = base_r;         vout = base_w;         } \
    else if (which == 1) { Cq = d_Cyx; vin = base_r;         vold = base_r + N;     vout = base_w + N;     } \
    else if (which == 2) { Cq = d_Cxx; vin = base_r + 2 * N; vold = base_r + 2 * N; vout = base_w + 2 * N; } \
    else                 { Cq = d_Cyy; vin = base_r + 3 * N; vold = base_r + 3 * N; vout = base_w + 3 * N; }

#define DEC2(uw, vka, vkb, a0, a1) \
    { float q0 = __uint_as_float(0x4B000000u | ((uw) & 0xFFFFu)); \
      float q1 = __uint_as_float(0x4B000000u | ((uw) >> 16)); \
      a0 = fmaf(q0, nQK, (vka)); \
      a1 = fmaf(q1, nQK, (vkb)); }

// ---------------- two-pass LSE (bootstrap; also writes d_ref) ----------------
__global__ __launch_bounds__(256, 2) void lse2_kernel(int parity) {
    int row0 = blockIdx.x * ROWS;
    int which = blockIdx.y;
    int tid = threadIdx.x;
    LSE_SELECT();
    float* refp = &d_ref[which][0];

    const float nQK = -QK;
    const float BIG = QK * 8388608.0f;   // exact: QK * 2^23 (decode bias)
    const float4* V4 = (const float4*)vin;

    float vrK[4][8];
    #pragma unroll
    for (int it = 0; it < 4; it++) {
        int base = it * 256 + tid;
        float4 v0 = V4[base * 2];
        float4 v1 = V4[base * 2 + 1];
        vrK[it][0] = fmaf(v0.x, KC, BIG); vrK[it][1] = fmaf(v0.y, KC, BIG);
        vrK[it][2] = fmaf(v0.z, KC, BIG); vrK[it][3] = fmaf(v0.w, KC, BIG);
        vrK[it][4] = fmaf(v1.x, KC, BIG); vrK[it][5] = fmaf(v1.y, KC, BIG);
        vrK[it][6] = fmaf(v1.z, KC, BIG); vrK[it][7] = fmaf(v1.w, KC, BIG);
    }

    const unsigned short* Cb = Cq + (size_t)row0 * N;
    uint4 cur[4], nxt[4], nxt2[4];
    #pragma unroll
    for (int it = 0; it < 4; it++)
        cur[it] = ((const uint4*)Cb)[it * 256 + tid];
    {
        const uint4* Cn = (const uint4*)(Cb + (size_t)N);
        #pragma unroll
        for (int it = 0; it < 4; it++)
            nxt[it] = Cn[it * 256 + tid];
    }

    __shared__ float sm[8];
    __shared__ float ssum[8];
    int w = tid >> 5, lane = tid & 31;

    #pragma unroll 4
    for (int r = 0; r < ROWS; r++) {
        if (r + 2 < ROWS) {
            const uint4* Cn = (const uint4*)(Cb + (size_t)(r + 2) * N);
            #pragma unroll
            for (int it = 0; it < 4; it++) nxt2[it] = Cn[it * 256 + tid];
        }

        float gm[4];
        float m = -CUDART_INF_F;
        #pragma unroll
        for (int it = 0; it < 4; it++) {
            float a0, a1, a2, a3, a4, a5, a6, a7;
            DEC2(cur[it].x, vrK[it][0], vrK[it][1], a0, a1);
            DEC2(cur[it].y, vrK[it][2], vrK[it][3], a2, a3);
            DEC2(cur[it].z, vrK[it][4], vrK[it][5], a4, a5);
            DEC2(cur[it].w, vrK[it][6], vrK[it][7], a6, a7);
            float g = fmaxf(fmaxf(fmaxf(a0, a1), fmaxf(a2, a3)),
                            fmaxf(fmaxf(a4, a5), fmaxf(a6, a7)));
            gm[it] = g;
            m = fmaxf(m, g);
        }
        #pragma unroll
        for (int o = 16; o; o >>= 1) m = fmaxf(m, __shfl_xor_sync(0xffffffffu, m, o));
        if (lane == 0) sm[w] = m;
        __syncthreads();
        float Mx = sm[0];
        #pragma unroll
        for (int i = 1; i < 8; i++) Mx = fmaxf(Mx, sm[i]);

        float thr = Mx - 25.f;
        float s = 0.f;
        #pragma unroll
        for (int it = 0; it < 4; it++) {
            if (__ballot_sync(0xffffffffu, gm[it] > thr)) {
                float a0, a1, a2, a3, a4, a5, a6, a7;
                DEC2(cur[it].x, vrK[it][0], vrK[it][1], a0, a1);
                DEC2(cur[it].y, vrK[it][2], vrK[it][3], a2, a3);
                DEC2(cur[it].z, vrK[it][4], vrK[it][5], a4, a5);
                DEC2(cur[it].w, vrK[it][6], vrK[it][7], a6, a7);
                if (a0 > thr) s += exp2f(a0 - Mx);
                if (a1 > thr) s += exp2f(a1 - Mx);
                if (a2 > thr) s += exp2f(a2 - Mx);
                if (a3 > thr) s += exp2f(a3 - Mx);
                if (a4 > thr) s += exp2f(a4 - Mx);
                if (a5 > thr) s += exp2f(a5 - Mx);
                if (a6 > thr) s += exp2f(a6 - Mx);
                if (a7 > thr) s += exp2f(a7 - Mx);
            }
        }
        #pragma unroll
        for (int o = 16; o; o >>= 1) s += __shfl_xor_sync(0xffffffffu, s, o);
        if (lane == 0) ssum[w] = s;
        __syncthreads();

        if (tid == 0) {
            float S = ssum[0];
            #pragma unroll
            for (int i = 1; i < 8; i++) S += ssum[i];
            float lse2 = Mx + log2f(S);
            vout[row0 + r] = 0.5f * (vold[row0 + r] + EPSLOGN - EPSLN2 * lse2);
            refp[row0 + r] = lse2;     // reference for the single-pass phase
        }

        #pragma unroll
        for (int it = 0; it < 4; it++) { cur[it] = nxt[it]; nxt[it] = nxt2[it]; }
    }
}

// ---------------- fused single-pass kernel ----------------
// y=0: Cxy read ONCE -> f row-sums (ref-based) + per-band column partial sums
//      (ref-based, no max needed) stored to d_colpart[band][col].
// y=1: Cxx -> p update (lse1 path). y=2: Cyy -> q update.
// mode=0: damped update; mode=1: extrapolation.
__global__ __launch_bounds__(256, 2) void fused_kernel(int parity, int mode) {
    int row0 = blockIdx.x * ROWS;
    int tid = threadIdx.x;
    int w = tid >> 5, lane = tid & 31;
    const float nQK = -QK;
    const float BIG = QK * 8388608.0f;

    if (blockIdx.y != 0) {
        // ---- p/q path: single-pass ref-LSE over Cxx / Cyy ----
        int which = blockIdx.y + 1;    // 2 or 3
        LSE_SELECT();
        if (mode) vout = &d_evec[which][0];
        float* refp = &d_ref[which][0];
        const float4* V4 = (const float4*)vin;

        float vrK[4][8];
        #pragma unroll
        for (int it = 0; it < 4; it++) {
            int base = it * 256 + tid;
            float4 v0 = V4[base * 2];
            float4 v1 = V4[base * 2 + 1];
            vrK[it][0] = fmaf(v0.x, KC, BIG); vrK[it][1] = fmaf(v0.y, KC, BIG);
            vrK[it][2] = fmaf(v0.z, KC, BIG); vrK[it][3] = fmaf(v0.w, KC, BIG);
            vrK[it][4] = fmaf(v1.x, KC, BIG); vrK[it][5] = fmaf(v1.y, KC, BIG);
            vrK[it][6] = fmaf(v1.z, KC, BIG); vrK[it][7] = fmaf(v1.w, KC, BIG);
        }

        const unsigned short* Cb = Cq + (size_t)row0 * N;
        uint4 cur[4], nxt[4], nxt2[4];
        #pragma unroll
        for (int it = 0; it < 4; it++)
            cur[it] = ((const uint4*)Cb)[it * 256 + tid];
        {
            const uint4* Cn = (const uint4*)(Cb + (size_t)N);
            #pragma unroll
            for (int it = 0; it < 4; it++)
                nxt[it] = Cn[it * 256 + tid];
        }

        __shared__ float ssum[2][8];
        #pragma unroll 4
        for (int r = 0; r < ROWS; r++) {
            if (r + 2 < ROWS) {
                const uint4* Cn = (const uint4*)(Cb + (size_t)(r + 2) * N);
                #pragma unroll
                for (int it = 0; it < 4; it++) nxt2[it] = Cn[it * 256 + tid];
            }
            float R = refp[row0 + r];
            float thr = R - 30.f;
            float s = 0.f;
            #pragma unroll
            for (int it = 0; it < 4; it++) {
                float a0, a1, a2, a3, a4, a5, a6, a7;
                DEC2(cur[it].x, vrK[it][0], vrK[it][1], a0, a1);
                DEC2(cur[it].y, vrK[it][2], vrK[it][3], a2, a3);
                DEC2(cur[it].z, vrK[it][4], vrK[it][5], a4, a5);
                DEC2(cur[it].w, vrK[it][6], vrK[it][7], a6, a7);
                float g = fmaxf(fmaxf(fmaxf(a0, a1), fmaxf(a2, a3)),
                                fmaxf(fmaxf(a4, a5), fmaxf(a6, a7)));
                if (__ballot_sync(0xffffffffu, g > thr)) {
                    if (a0 > thr) s += exp2f(a0 - R);
                    if (a1 > thr) s += exp2f(a1 - R);
                    if (a2 > thr) s += exp2f(a2 - R);
                    if (a3 > thr) s += exp2f(a3 - R);
                    if (a4 > thr) s += exp2f(a4 - R);
                    if (a5 > thr) s += exp2f(a5 - R);
                    if (a6 > thr) s += exp2f(a6 - R);
                    if (a7 > thr) s += exp2f(a7 - R);
                }
            }
            #pragma unroll
            for (int o = 16; o; o >>= 1) s += __shfl_xor_sync(0xffffffffu, s, o);
            if (lane == 0) ssum[r & 1][w] = s;
            __syncthreads();
            if (tid == 0) {
                float S = ssum[r & 1][0];
                #pragma unroll
                for (int i = 1; i < 8; i++) S += ssum[r & 1][i];
                float lse2 = R + log2f(S);
                float val;
                if (mode) val = EPSLOGN - EPSLN2 * lse2;
                else      val = 0.5f * (vold[row0 + r] + EPSLOGN - EPSLN2 * lse2);
                vout[row0 + r] = val;
                if (!mode) refp[row0 + r] = lse2;
            }
            #pragma unroll
            for (int it = 0; it < 4; it++) { cur[it] = nxt[it]; nxt[it] = nxt2[it]; }
        }
        return;
    }

    // ---- y == 0: fused Cxy path (f rows + g column partials) ----
    const float* f_old = &d_vecs[parity][0][0];
    const float* g_old = &d_vecs[parity][1][0];
    float* f_out = mode ? &d_evec[0][0] : &d_vecs[parity ^ 1][0][0];
    float* refF = &d_ref[0][0];
    const float* refG = &d_ref[1][0];

    // vgK: pre-scaled g operand in registers
    float vgK[4][8];
    {
        const float4* V4 = (const float4*)g_old;
        #pragma unroll
        for (int it = 0; it < 4; it++) {
            int base = it * 256 + tid;
            float4 v0 = V4[base * 2];
            float4 v1 = V4[base * 2 + 1];
            vgK[it][0] = fmaf(v0.x, KC, BIG); vgK[it][1] = fmaf(v0.y, KC, BIG);
            vgK[it][2] = fmaf(v0.z, KC, BIG); vgK[it][3] = fmaf(v0.w, KC, BIG);
            vgK[it][4] = fmaf(v1.x, KC, BIG); vgK[it][5] = fmaf(v1.y, KC, BIG);
            vgK[it][6] = fmaf(v1.z, KC, BIG); vgK[it][7] = fmaf(v1.w, KC, BIG);
        }
    }
    // w = BIG - refG[j] in smem (column decode operand)
    __shared__ float4 wA[N / 8];
    __shared__ float4 wB[N / 8];
    {
        const float4* R4 = (const float4*)refG;
        for (int g = tid; g < N / 8; g += 256) {
            float4 r0 = R4[2 * g], r1 = R4[2 * g + 1];
            wA[g] = make_float4(BIG - r0.x, BIG - r0.y, BIG - r0.z, BIG - r0.w);
            wB[g] = make_float4(BIG - r1.x, BIG - r1.y, BIG - r1.z, BIG - r1.w);
        }
    }
    __syncthreads();

    float colacc[4][8];
    #pragma unroll
    for (int it = 0; it < 4; it++)
        #pragma unroll
        for (int e = 0; e < 8; e++) colacc[it][e] = 0.f;

    const unsigned short* Cb = d_Cxy + (size_t)row0 * N;
    uint4 cur[4], nxt[4];
    #pragma unroll
    for (int it = 0; it < 4; it++)
        cur[it] = ((const uint4*)Cb)[it * 256 + tid];

    __shared__ float ssum[2][8];

    #pragma unroll 1
    for (int r = 0; r < ROWS; r++) {
        if (r + 1 < ROWS) {
            const uint4* Cn = (const uint4*)(Cb + (size_t)(r + 1) * N);
            #pragma unroll
            for (int it = 0; it < 4; it++) nxt[it] = Cn[it * 256 + tid];
        }

        float R = refF[row0 + r];
        float thr = R - 30.f;
        float fK = f_old[row0 + r] * KC;
        float thrC = -30.f - fK;      // skip if c < thrC  (c + fK < -30)
        float s = 0.f;

        #pragma unroll
        for (int it = 0; it < 4; it++) {
            // row decode (f update, operand g)
            float a0, a1, a2, a3, a4, a5, a6, a7;
            DEC2(cur[it].x, vgK[it][0], vgK[it][1], a0, a1);
            DEC2(cur[it].y, vgK[it][2], vgK[it][3], a2, a3);
            DEC2(cur[it].z, vgK[it][4], vgK[it][5], a4, a5);
            DEC2(cur[it].w, vgK[it][6], vgK[it][7], a6, a7);
            float g8 = fmaxf(fmaxf(fmaxf(a0, a1), fmaxf(a2, a3)),
                             fmaxf(fmaxf(a4, a5), fmaxf(a6, a7)));
            if (__ballot_sync(0xffffffffu, g8 > thr)) {
                if (a0 > thr) s += exp2f(a0 - R);
                if (a1 > thr) s += exp2f(a1 - R);
                if (a2 > thr) s += exp2f(a2 - R);
                if (a3 > thr) s += exp2f(a3 - R);
                if (a4 > thr) s += exp2f(a4 - R);
                if (a5 > thr) s += exp2f(a5 - R);
                if (a6 > thr) s += exp2f(a6 - R);
                if (a7 > thr) s += exp2f(a7 - R);
            }

            // column decode (g partial, operand -refG): c = -q*QK - refG[j]
            int g = it * 256 + tid;
            float4 va = wA[g], vb = wB[g];
            float c0, c1, c2, c3, c4, c5, c6, c7;
            DEC2(cur[it].x, va.x, va.y, c0, c1);
            DEC2(cur[it].y, va.z, va.w, c2, c3);
            DEC2(cur[it].z, vb.x, vb.y, c4, c5);
            DEC2(cur[it].w, vb.z, vb.w, c6, c7);
            float cmax = fmaxf(fmaxf(fmaxf(c0, c1), fmaxf(c2, c3)),
                               fmaxf(fmaxf(c4, c5), fmaxf(c6, c7)));
            if (cmax > thrC) {
                if (c0 > thrC) colacc[it][0] += exp2f(c0 + fK);
                if (c1 > thrC) colacc[it][1] += exp2f(c1 + fK);
                if (c2 > thrC) colacc[it][2] += exp2f(c2 + fK);
                if (c3 > thrC) colacc[it][3] += exp2f(c3 + fK);
                if (c4 > thrC) colacc[it][4] += exp2f(c4 + fK);
                if (c5 > thrC) colacc[it][5] += exp2f(c5 + fK);
                if (c6 > thrC) colacc[it][6] += exp2f(c6 + fK);
                if (c7 > thrC) colacc[it][7] += exp2f(c7 + fK);
            }
        }

        #pragma unroll
        for (int o = 16; o; o >>= 1) s += __shfl_xor_sync(0xffffffffu, s, o);
        if (lane == 0) ssum[r & 1][w] = s;
        __syncthreads();
        if (tid == 0) {
            float S = ssum[r & 1][0];
            #pragma unroll
            for (int i = 1; i < 8; i++) S += ssum[r & 1][i];
            float lse2 = R + log2f(S);
            float val;
            if (mode) val = EPSLOGN - EPSLN2 * lse2;
            else      val = 0.5f * (f_old[row0 + r] + EPSLOGN - EPSLN2 * lse2);
            f_out[row0 + r] = val;
            if (!mode) refF[row0 + r] = lse2;
        }

        #pragma unroll
        for (int it = 0; it < 4; it++) cur[it] = nxt[it];
    }

    // store column partials (deterministic; reduced by colsum_kernel)
    float* cp = &d_colpart[blockIdx.x][0];
    #pragma unroll
    for (int it = 0; it < 4; it++) {
        int g = it * 256 + tid;
        *(float4*)&cp[8 * g]     = make_float4(colacc[it][0], colacc[it][1], colacc[it][2], colacc[it][3]);
        *(float4*)&cp[8 * g + 4] = make_float4(colacc[it][4], colacc[it][5], colacc[it][6], colacc[it][7]);
    }
}

// ---------------- column-sum epilogue: g update ----------------
__global__ void colsum_kernel(int parity, int mode) {
    int j = blockIdx.x * 256 + threadIdx.x;
    float s = 0.f;
    #pragma unroll 8
    for (int b = 0; b < NBLK; b++) s += d_colpart[b][j];
    float R = d_ref[1][j];
    float lse2 = R + log2f(s);
    if (mode) {
        d_evec[1][j] = EPSLOGN - EPSLN2 * lse2;
    } else {
        d_vecs[parity ^ 1][1][j] =
            0.5f * (d_vecs[parity][1][j] + EPSLOGN - EPSLN2 * lse2);
        d_ref[1][j] = lse2;
    }
}

// ---------------- final scalar reduction ----------------
__global__ void final_kernel(float* out) {
    __shared__ double sh[32];
    double acc = 0.0;
    for (int i = threadIdx.x; i < N; i += 1024) {
        acc += (double)d_evec[0][i] - (double)d_evec[2][i]
             + (double)d_evec[1][i] - (double)d_evec[3][i];
    }
    #pragma unroll
    for (int o = 16; o; o >>= 1) acc += __shfl_down_sync(0xffffffffu, acc, o);
    int w = threadIdx.x >> 5, lane = threadIdx.x & 31;
    if (lane == 0) sh[w] = acc;
    __syncthreads();
    if (threadIdx.x < 32) {
        double a = sh[threadIdx.x];
        #pragma unroll
        for (int o = 16; o; o >>= 1) a += __shfl_down_sync(0xffffffffu, a, o);
        if (threadIdx.x == 0) out[0] = (float)(a / (double)N);
    }
}

// ---------------- launch ----------------
extern "C" void kernel_launch(void* const* d_in, const int* in_sizes, int n_in,
                              void* d_out, int out_size) {
    (void)in_sizes; (void)n_in; (void)out_size;
    const float* x  = (const float*)d_in[0];   // xt
    const float* pz = (const float*)d_in[1];   // xs

    rownorm_kernel<<<dim3(N / 8, 2), 256>>>(x, pz);
    init_kernel<<<(2 * 4 * N + 255) / 256, 256>>>();

    dim3 gg(64, 64);
    gemm_dist_kernel<<<gg, 256>>>(x, pz, 0);
    gemm_dist_kernel<<<gg, 256>>>(x, pz, 1);
    gemm_dist_kernel<<<gg, 256>>>(x, pz, 2);

    for (int it = 0; it < BOOT; ++it)
        lse2_kernel<<<dim3(NBLK, 4), 256>>>(it & 1);        // two-pass, writes refs

    for (int it = BOOT; it < 50; ++it) {
        fused_kernel<<<dim3(NBLK, 3), 256>>>(it & 1, 0);    // f,p,q + col partials
        colsum_kernel<<<N / 256, 256>>>(it & 1, 0);         // g
    }

    fused_kernel<<<dim3(NBLK, 3), 256>>>(0, 1);             // extrapolation
    colsum_kernel<<<N / 256, 256>>>(0, 1);
    final_kernel<<<1, 1024>>>((float*)d_out);
}

// round 15
// speedup vs baseline: 1.8006x; 1.8006x over previous
#include <cuda_runtime.h>
#include <math_constants.h>

#define N 8192
#define D 512
#define ROWS 16      // rows per LSE block (bootstrap kernel)
#define BOOT 12      // bootstrap iterations using two-pass dense kernel
#define NBLK (N / ROWS)
#define CAP  2048    // sparse entries per row (avg ~220 expected)
#define MARGIN 45.0f // build selection margin (base-2 exponent units)

// quantization: C stored as uint16, value = q / QSCALE, QSCALE = 1600 (max 40.96)
#define QSCALE    1600.0f
#define KC        28.85390081777927f          // 1/(eps*ln2)
#define QK        (KC / QSCALE)
#define EPSLN2    0.034657359027997264f       // eps*ln2
#define EPSLOGN   0.4505456673639644f         // eps*ln(8192)

// ---------------- device scratch (no allocations allowed) ----------------
__device__ __align__(256) unsigned short d_Cxy[67108864];   // 128MB each
__device__ __align__(256) unsigned short d_Cyx[67108864];
__device__ __align__(256) unsigned short d_Cxx[67108864];
__device__ __align__(256) unsigned short d_Cyy[67108864];
__device__ __align__(256) unsigned int d_sparse[4][N][CAP]; // 256MB sparse lists
__device__ __align__(256) int d_scount[4][N];
__device__ __align__(256) float d_sx[N];
__device__ __align__(256) float d_sy[N];
__device__ __align__(256) float d_vecs[2][4][N];   // ping-pong f,g,p,q
__device__ __align__(256) float d_evec[4][N];      // f_e, g_e, p_e, q_e
__device__ __align__(256) float d_ref[4][N];       // last row-lse2 per matrix

// ---------------- row squared-norms ----------------
__global__ void rownorm_kernel(const float* __restrict__ X, const float* __restrict__ PZ) {
    const float* src = (blockIdx.y == 0) ? PZ : X;    // y=0: xs=prior_z -> sx
    float* dst = (blockIdx.y == 0) ? d_sx : d_sy;
    int row = blockIdx.x * 8 + (threadIdx.x >> 5);
    int lane = threadIdx.x & 31;
    const float4* xr = (const float4*)(src + (size_t)row * D);
    float s = 0.f;
    #pragma unroll
    for (int t = lane; t < D / 4; t += 32) {
        float4 v = xr[t];
        s += v.x * v.x + v.y * v.y + v.z * v.z + v.w * v.w;
    }
    #pragma unroll
    for (int o = 16; o; o >>= 1) s += __shfl_down_sync(0xffffffffu, s, o);
    if (lane == 0) dst[row] = s;
}

__global__ void init_kernel() {
    int i = blockIdx.x * blockDim.x + threadIdx.x;
    if (i < 2 * 4 * N) ((float*)d_vecs)[i] = 0.f;
}

// ---------------- fused GEMM + distance + uint16 quantize ----------------
__global__ __launch_bounds__(256) void gemm_dist_kernel(
    const float* __restrict__ X, const float* __restrict__ PZ, int which)
{
    const float *A, *B, *sA, *sB;
    unsigned short *C, *Cm;
    bool sym;
    if (which == 0)      { A = PZ; B = X;  sA = d_sx; sB = d_sy; C = d_Cxy; Cm = d_Cyx; sym = false; }
    else if (which == 1) { A = PZ; B = PZ; sA = d_sx; sB = d_sx; C = d_Cxx; Cm = d_Cxx; sym = true;  }
    else                 { A = X;  B = X;  sA = d_sy; sB = d_sy; C = d_Cyy; Cm = d_Cyy; sym = true;  }

    int bx = blockIdx.x, by = blockIdx.y;
    if (sym && by > bx) return;

    __shared__ float As[16][132];
    __shared__ float Bs[16][132];
    __shared__ unsigned int ts[128][65];

    int tid = threadIdx.x;
    int ty = tid >> 4, tx = tid & 15;
    int trow = ty * 8, tcol = tx * 8;

    float acc[8][8];
    #pragma unroll
    for (int i = 0; i < 8; i++)
        #pragma unroll
        for (int j = 0; j < 8; j++) acc[i][j] = 0.f;

    const float* Ab = A + (size_t)by * 128 * D;
    const float* Bb = B + (size_t)bx * 128 * D;

    for (int k0 = 0; k0 < D; k0 += 16) {
        #pragma unroll
        for (int l = 0; l < 2; l++) {
            int idx = tid + l * 256;
            int r = idx >> 2;
            int c = (idx & 3) << 2;
            float4 av = *(const float4*)(Ab + (size_t)r * D + k0 + c);
            As[c + 0][r] = av.x; As[c + 1][r] = av.y; As[c + 2][r] = av.z; As[c + 3][r] = av.w;
            float4 bv = *(const float4*)(Bb + (size_t)r * D + k0 + c);
            Bs[c + 0][r] = bv.x; Bs[c + 1][r] = bv.y; Bs[c + 2][r] = bv.z; Bs[c + 3][r] = bv.w;
        }
        __syncthreads();
        #pragma unroll
        for (int kk = 0; kk < 16; kk++) {
            float ar[8], br[8];
            #pragma unroll
            for (int i = 0; i < 8; i++) ar[i] = As[kk][trow + i];
            #pragma unroll
            for (int j = 0; j < 8; j++) br[j] = Bs[kk][tcol + j];
            #pragma unroll
            for (int i = 0; i < 8; i++)
                #pragma unroll
                for (int j = 0; j < 8; j++)
                    acc[i][j] = fmaf(ar[i], br[j], acc[i][j]);
        }
        __syncthreads();
    }

    int gr0 = by * 128, gc0 = bx * 128;
    float sa[8], sb[8];
    #pragma unroll
    for (int i = 0; i < 8; i++) sa[i] = sA[gr0 + trow + i];
    #pragma unroll
    for (int j = 0; j < 8; j++) sb[j] = sB[gc0 + tcol + j];

    #pragma unroll
    for (int i = 0; i < 8; i++) {
        #pragma unroll
        for (int j = 0; j < 8; j += 2) {
            float sq0 = sa[i] + sb[j]     - 2.f * acc[i][j];
            float sq1 = sa[i] + sb[j + 1] - 2.f * acc[i][j + 1];
            float d0 = sqrtf(fmaxf(sq0, 1e-12f));
            float d1 = sqrtf(fmaxf(sq1, 1e-12f));
            unsigned int q0 = min(65535u, __float2uint_rn(d0 * QSCALE));
            unsigned int q1 = min(65535u, __float2uint_rn(d1 * QSCALE));
            ts[trow + i][(tcol + j) >> 1] = q0 | (q1 << 16);
        }
    }
    __syncthreads();

    for (int idx = tid; idx < 128 * 16; idx += 256) {
        int r = idx >> 4, seg = idx & 15;
        uint4 w;
        w.x = ts[r][seg * 4 + 0];
        w.y = ts[r][seg * 4 + 1];
        w.z = ts[r][seg * 4 + 2];
        w.w = ts[r][seg * 4 + 3];
        *(uint4*)&C[(size_t)(gr0 + r) * N + gc0 + seg * 8] = w;
    }
    for (int idx = tid; idx < 128 * 16; idx += 256) {
        int c = idx >> 4, seg = idx & 15;
        uint4 w;
        unsigned int sh = (c & 1) * 16;
        #pragma unroll
        for (int k = 0; k < 4; k++) {
            int r = seg * 8 + k * 2;
            unsigned int lo = (ts[r][c >> 1] >> sh) & 0xFFFFu;
            unsigned int hi = (ts[r + 1][c >> 1] >> sh) & 0xFFFFu;
            ((unsigned int*)&w)[k] = lo | (hi << 16);
        }
        *(uint4*)&Cm[(size_t)(gc0 + c) * N + gr0 + seg * 8] = w;
    }
}

// operand selection shared by LSE/build/sparse kernels
#define LSE_SELECT() \
    const float* base_r = &d_vecs[parity][0][0]; \
    float* base_w = &d_vecs[parity ^ 1][0][0]; \
    const unsigned short* Cq; const float* vin; const float* vold; float* vout; \
    if (which == 0)      { Cq = d_Cxy; vin = base_r + N;     vold = base_r;         vout = base_w;         } \
    else if (which == 1) { Cq = d_Cyx; vin = base_r;         vold = base_r + N;     vout = base_w + N;     } \
    else if (which == 2) { Cq = d_Cxx; vin = base_r + 2 * N; vold = base_r + 2 * N; vout = base_w + 2 * N; } \
    else                 { Cq = d_Cyy; vin = base_r + 3 * N; vold = base_r + 3 * N; vout = base_w + 3 * N; }

#define DEC2(uw, vka, vkb, a0, a1) \
    { float q0 = __uint_as_float(0x4B000000u | ((uw) & 0xFFFFu)); \
      float q1 = __uint_as_float(0x4B000000u | ((uw) >> 16)); \
      a0 = fmaf(q0, nQK, (vka)); \
      a1 = fmaf(q1, nQK, (vkb)); }

// ---------------- two-pass dense LSE (bootstrap; writes d_ref) ----------------
__global__ __launch_bounds__(256, 2) void lse2_kernel(int parity) {
    int row0 = blockIdx.x * ROWS;
    int which = blockIdx.y;
    int tid = threadIdx.x;
    LSE_SELECT();
    float* refp = &d_ref[which][0];

    const float nQK = -QK;
    const float BIG = QK * 8388608.0f;   // exact: QK * 2^23 (decode bias)
    const float4* V4 = (const float4*)vin;

    float vrK[4][8];
    #pragma unroll
    for (int it = 0; it < 4; it++) {
        int base = it * 256 + tid;
        float4 v0 = V4[base * 2];
        float4 v1 = V4[base * 2 + 1];
        vrK[it][0] = fmaf(v0.x, KC, BIG); vrK[it][1] = fmaf(v0.y, KC, BIG);
        vrK[it][2] = fmaf(v0.z, KC, BIG); vrK[it][3] = fmaf(v0.w, KC, BIG);
        vrK[it][4] = fmaf(v1.x, KC, BIG); vrK[it][5] = fmaf(v1.y, KC, BIG);
        vrK[it][6] = fmaf(v1.z, KC, BIG); vrK[it][7] = fmaf(v1.w, KC, BIG);
    }

    const unsigned short* Cb = Cq + (size_t)row0 * N;
    uint4 cur[4], nxt[4], nxt2[4];
    #pragma unroll
    for (int it = 0; it < 4; it++)
        cur[it] = ((const uint4*)Cb)[it * 256 + tid];
    {
        const uint4* Cn = (const uint4*)(Cb + (size_t)N);
        #pragma unroll
        for (int it = 0; it < 4; it++)
            nxt[it] = Cn[it * 256 + tid];
    }

    __shared__ float sm[8];
    __shared__ float ssum[8];
    int w = tid >> 5, lane = tid & 31;

    #pragma unroll 4
    for (int r = 0; r < ROWS; r++) {
        if (r + 2 < ROWS) {
            const uint4* Cn = (const uint4*)(Cb + (size_t)(r + 2) * N);
            #pragma unroll
            for (int it = 0; it < 4; it++) nxt2[it] = Cn[it * 256 + tid];
        }

        float gm[4];
        float m = -CUDART_INF_F;
        #pragma unroll
        for (int it = 0; it < 4; it++) {
            float a0, a1, a2, a3, a4, a5, a6, a7;
            DEC2(cur[it].x, vrK[it][0], vrK[it][1], a0, a1);
            DEC2(cur[it].y, vrK[it][2], vrK[it][3], a2, a3);
            DEC2(cur[it].z, vrK[it][4], vrK[it][5], a4, a5);
            DEC2(cur[it].w, vrK[it][6], vrK[it][7], a6, a7);
            float g = fmaxf(fmaxf(fmaxf(a0, a1), fmaxf(a2, a3)),
                            fmaxf(fmaxf(a4, a5), fmaxf(a6, a7)));
            gm[it] = g;
            m = fmaxf(m, g);
        }
        #pragma unroll
        for (int o = 16; o; o >>= 1) m = fmaxf(m, __shfl_xor_sync(0xffffffffu, m, o));
        if (lane == 0) sm[w] = m;
        __syncthreads();
        float Mx = sm[0];
        #pragma unroll
        for (int i = 1; i < 8; i++) Mx = fmaxf(Mx, sm[i]);

        float thr = Mx - 25.f;
        float s = 0.f;
        #pragma unroll
        for (int it = 0; it < 4; it++) {
            if (__ballot_sync(0xffffffffu, gm[it] > thr)) {
                float a0, a1, a2, a3, a4, a5, a6, a7;
                DEC2(cur[it].x, vrK[it][0], vrK[it][1], a0, a1);
                DEC2(cur[it].y, vrK[it][2], vrK[it][3], a2, a3);
                DEC2(cur[it].z, vrK[it][4], vrK[it][5], a4, a5);
                DEC2(cur[it].w, vrK[it][6], vrK[it][7], a6, a7);
                if (a0 > thr) s += exp2f(a0 - Mx);
                if (a1 > thr) s += exp2f(a1 - Mx);
                if (a2 > thr) s += exp2f(a2 - Mx);
                if (a3 > thr) s += exp2f(a3 - Mx);
                if (a4 > thr) s += exp2f(a4 - Mx);
                if (a5 > thr) s += exp2f(a5 - Mx);
                if (a6 > thr) s += exp2f(a6 - Mx);
                if (a7 > thr) s += exp2f(a7 - Mx);
            }
        }
        #pragma unroll
        for (int o = 16; o; o >>= 1) s += __shfl_xor_sync(0xffffffffu, s, o);
        if (lane == 0) ssum[w] = s;
        __syncthreads();

        if (tid == 0) {
            float S = ssum[0];
            #pragma unroll
            for (int i = 1; i < 8; i++) S += ssum[i];
            float lse2 = Mx + log2f(S);
            vout[row0 + r] = 0.5f * (vold[row0 + r] + EPSLOGN - EPSLN2 * lse2);
            refp[row0 + r] = lse2;
        }

        #pragma unroll
        for (int it = 0; it < 4; it++) { cur[it] = nxt[it]; nxt[it] = nxt2[it]; }
    }
}

// ---------------- sparse list build (one warp per row, deterministic) -------
// Selects entries with a = v*KC - q*QK > ref - MARGIN, compacted in column
// order via warp ballot. Entry = col | (q << 16).
__global__ __launch_bounds__(256) void build_kernel(int parity) {
    int which = blockIdx.y;
    int tid = threadIdx.x;
    LSE_SELECT();
    (void)vold; (void)vout; (void)base_w;
    const float* refp = &d_ref[which][0];
    const float nQK = -QK;
    const float BIG = QK * 8388608.0f;

    __shared__ float vK[N];
    {
        const float4* V4 = (const float4*)vin;
        for (int g = tid; g < N / 4; g += 256) {
            float4 v = V4[g];
            vK[4 * g + 0] = fmaf(v.x, KC, BIG);
            vK[4 * g + 1] = fmaf(v.y, KC, BIG);
            vK[4 * g + 2] = fmaf(v.z, KC, BIG);
            vK[4 * g + 3] = fmaf(v.w, KC, BIG);
        }
    }
    __syncthreads();

    int w = tid >> 5, lane = tid & 31;
    int row = blockIdx.x * 8 + w;
    const uint2* Crow = (const uint2*)(Cq + (size_t)row * N);   // 4 ushorts each
    unsigned int* out = &d_sparse[which][row][0];
    float sel = refp[row] - MARGIN;
    int cnt = 0;

    for (int t = 0; t < N / 128; t++) {
        uint2 u = Crow[t * 32 + lane];
        unsigned int qs[4] = { u.x & 0xFFFFu, u.x >> 16, u.y & 0xFFFFu, u.y >> 16 };
        #pragma unroll
        for (int e = 0; e < 4; e++) {
            int col = t * 128 + lane * 4 + e;
            unsigned int q = qs[e];
            float a = fmaf(__uint_as_float(0x4B000000u | q), nQK, vK[col]);
            bool pred = a > sel;
            unsigned int mask = __ballot_sync(0xffffffffu, pred);
            int pos = cnt + __popc(mask & ((1u << lane) - 1u));
            if (pred && pos < CAP) out[pos] = (unsigned int)col | (q << 16);
            cnt += __popc(mask);
        }
    }
    if (lane == 0) d_scount[which][row] = min(cnt, CAP);
}

// ---------------- sparse ref-based LSE iteration ----------------
// One warp per row (4 rows serially), entries from d_sparse only.
// mode=0: damped update + ref refresh; mode=1: extrapolation.
__global__ __launch_bounds__(256) void sparse_kernel(int parity, int mode) {
    int which = blockIdx.y;
    int tid = threadIdx.x;
    LSE_SELECT();
    if (mode) vout = &d_evec[which][0];
    float* refp = &d_ref[which][0];
    const float nQK = -QK;
    const float BIG = QK * 8388608.0f;
    (void)Cq;

    __shared__ float vK[N];
    {
        const float4* V4 = (const float4*)vin;
        for (int g = tid; g < N / 4; g += 256) {
            float4 v = V4[g];
            vK[4 * g + 0] = fmaf(v.x, KC, BIG);
            vK[4 * g + 1] = fmaf(v.y, KC, BIG);
            vK[4 * g + 2] = fmaf(v.z, KC, BIG);
            vK[4 * g + 3] = fmaf(v.w, KC, BIG);
        }
    }
    __syncthreads();

    int w = tid >> 5, lane = tid & 31;
    int row0 = blockIdx.x * 32 + w * 4;

    #pragma unroll 1
    for (int r = 0; r < 4; r++) {
        int row = row0 + r;
        int cnt = d_scount[which][row];
        float R = refp[row];
        float thr = R - 30.f;
        float s = 0.f;
        const unsigned int* sp = &d_sparse[which][row][0];
        for (int t = lane; t < cnt; t += 32) {
            unsigned int e = sp[t];
            unsigned int q = e >> 16;
            int col = e & 0xFFFFu;
            float a = fmaf(__uint_as_float(0x4B000000u | q), nQK, vK[col]);
            if (a > thr) s += exp2f(a - R);
        }
        #pragma unroll
        for (int o = 16; o; o >>= 1) s += __shfl_xor_sync(0xffffffffu, s, o);

        if (lane == 0) {
            float lse2 = R + log2f(s);
            float val;
            if (mode) val = EPSLOGN - EPSLN2 * lse2;
            else      val = 0.5f * (vold[row] + EPSLOGN - EPSLN2 * lse2);
            vout[row] = val;
            if (!mode) refp[row] = lse2;
        }
    }
}

// ---------------- final scalar reduction ----------------
__global__ void final_kernel(float* out) {
    __shared__ double sh[32];
    double acc = 0.0;
    for (int i = threadIdx.x; i < N; i += 1024) {
        acc += (double)d_evec[0][i] - (double)d_evec[2][i]
             + (double)d_evec[1][i] - (double)d_evec[3][i];
    }
    #pragma unroll
    for (int o = 16; o; o >>= 1) acc += __shfl_down_sync(0xffffffffu, acc, o);
    int w = threadIdx.x >> 5, lane = threadIdx.x & 31;
    if (lane == 0) sh[w] = acc;
    __syncthreads();
    if (threadIdx.x < 32) {
        double a = sh[threadIdx.x];
        #pragma unroll
        for (int o = 16; o; o >>= 1) a += __shfl_down_sync(0xffffffffu, a, o);
        if (threadIdx.x == 0) out[0] = (float)(a / (double)N);
    }
}

// ---------------- launch ----------------
extern "C" void kernel_launch(void* const* d_in, const int* in_sizes, int n_in,
                              void* d_out, int out_size) {
    (void)in_sizes; (void)n_in; (void)out_size;
    const float* x  = (const float*)d_in[0];   // xt
    const float* pz = (const float*)d_in[1];   // xs

    rownorm_kernel<<<dim3(N / 8, 2), 256>>>(x, pz);
    init_kernel<<<(2 * 4 * N + 255) / 256, 256>>>();

    dim3 gg(64, 64);
    gemm_dist_kernel<<<gg, 256>>>(x, pz, 0);
    gemm_dist_kernel<<<gg, 256>>>(x, pz, 1);
    gemm_dist_kernel<<<gg, 256>>>(x, pz, 2);

    for (int it = 0; it < BOOT; ++it)
        lse2_kernel<<<dim3(NBLK, 4), 256>>>(it & 1);     // dense two-pass, writes refs

    build_kernel<<<dim3(N / 8, 4), 256>>>(BOOT & 1);     // sparse candidate lists

    for (int it = BOOT; it < 50; ++it)
        sparse_kernel<<<dim3(N / 32, 4), 256>>>(it & 1, 0);

    sparse_kernel<<<dim3(N / 32, 4), 256>>>(0, 1);       // extrapolation (final vecs in slot 0)
    final_kernel<<<1, 1024>>>((float*)d_out);
}

// round 16
// speedup vs baseline: 2.1008x; 1.1667x over previous
#include <cuda_runtime.h>
#include <math_constants.h>

#define N 8192
#define D 512
#define ROWS 16      // rows per LSE block (bootstrap kernel)
#define BOOT 8       // bootstrap iterations using two-pass dense kernel
#define NBLK (N / ROWS)
#define CAP  2048    // sparse entries per row (avg ~220 expected)
#define MARGIN 45.0f // build selection margin (base-2 exponent units)

// quantization: C stored as uint16, value = q / QSCALE, QSCALE = 1600 (max 40.96)
#define QSCALE    1600.0f
#define KC        28.85390081777927f          // 1/(eps*ln2)
#define QK        (KC / QSCALE)
#define EPSLN2    0.034657359027997264f       // eps*ln2
#define EPSLOGN   0.4505456673639644f         // eps*ln(8192)

// ---------------- device scratch (no allocations allowed) ----------------
__device__ __align__(256) unsigned short d_Cxy[67108864];   // 128MB each
__device__ __align__(256) unsigned short d_Cyx[67108864];
__device__ __align__(256) unsigned short d_Cxx[67108864];
__device__ __align__(256) unsigned short d_Cyy[67108864];
__device__ __align__(256) unsigned int d_sparse[4][N][CAP]; // 256MB sparse lists
__device__ __align__(256) int d_scount[4][N];
__device__ __align__(256) float d_sx[N];
__device__ __align__(256) float d_sy[N];
__device__ __align__(256) float d_vecs[2][4][N];   // ping-pong f,g,p,q
__device__ __align__(256) float d_evec[4][N];      // f_e, g_e, p_e, q_e
__device__ __align__(256) float d_ref[4][N];       // last row-lse2 per matrix

// ---------------- row squared-norms ----------------
__global__ void rownorm_kernel(const float* __restrict__ X, const float* __restrict__ PZ) {
    const float* src = (blockIdx.y == 0) ? PZ : X;    // y=0: xs=prior_z -> sx
    float* dst = (blockIdx.y == 0) ? d_sx : d_sy;
    int row = blockIdx.x * 8 + (threadIdx.x >> 5);
    int lane = threadIdx.x & 31;
    const float4* xr = (const float4*)(src + (size_t)row * D);
    float s = 0.f;
    #pragma unroll
    for (int t = lane; t < D / 4; t += 32) {
        float4 v = xr[t];
        s += v.x * v.x + v.y * v.y + v.z * v.z + v.w * v.w;
    }
    #pragma unroll
    for (int o = 16; o; o >>= 1) s += __shfl_down_sync(0xffffffffu, s, o);
    if (lane == 0) dst[row] = s;
}

__global__ void init_kernel() {
    int i = blockIdx.x * blockDim.x + threadIdx.x;
    if (i < 2 * 4 * N) ((float*)d_vecs)[i] = 0.f;
}

// ---------------- fused GEMM + distance + uint16 quantize ----------------
__global__ __launch_bounds__(256) void gemm_dist_kernel(
    const float* __restrict__ X, const float* __restrict__ PZ, int which)
{
    const float *A, *B, *sA, *sB;
    unsigned short *C, *Cm;
    bool sym;
    if (which == 0)      { A = PZ; B = X;  sA = d_sx; sB = d_sy; C = d_Cxy; Cm = d_Cyx; sym = false; }
    else if (which == 1) { A = PZ; B = PZ; sA = d_sx; sB = d_sx; C = d_Cxx; Cm = d_Cxx; sym = true;  }
    else                 { A = X;  B = X;  sA = d_sy; sB = d_sy; C = d_Cyy; Cm = d_Cyy; sym = true;  }

    int bx = blockIdx.x, by = blockIdx.y;
    if (sym && by > bx) return;

    __shared__ float As[16][132];
    __shared__ float Bs[16][132];
    __shared__ unsigned int ts[128][65];

    int tid = threadIdx.x;
    int ty = tid >> 4, tx = tid & 15;
    int trow = ty * 8, tcol = tx * 8;

    float acc[8][8];
    #pragma unroll
    for (int i = 0; i < 8; i++)
        #pragma unroll
        for (int j = 0; j < 8; j++) acc[i][j] = 0.f;

    const float* Ab = A + (size_t)by * 128 * D;
    const float* Bb = B + (size_t)bx * 128 * D;

    for (int k0 = 0; k0 < D; k0 += 16) {
        #pragma unroll
        for (int l = 0; l < 2; l++) {
            int idx = tid + l * 256;
            int r = idx >> 2;
            int c = (idx & 3) << 2;
            float4 av = *(const float4*)(Ab + (size_t)r * D + k0 + c);
            As[c + 0][r] = av.x; As[c + 1][r] = av.y; As[c + 2][r] = av.z; As[c + 3][r] = av.w;
            float4 bv = *(const float4*)(Bb + (size_t)r * D + k0 + c);
            Bs[c + 0][r] = bv.x; Bs[c + 1][r] = bv.y; Bs[c + 2][r] = bv.z; Bs[c + 3][r] = bv.w;
        }
        __syncthreads();
        #pragma unroll
        for (int kk = 0; kk < 16; kk++) {
            float ar[8], br[8];
            #pragma unroll
            for (int i = 0; i < 8; i++) ar[i] = As[kk][trow + i];
            #pragma unroll
            for (int j = 0; j < 8; j++) br[j] = Bs[kk][tcol + j];
            #pragma unroll
            for (int i = 0; i < 8; i++)
                #pragma unroll
                for (int j = 0; j < 8; j++)
                    acc[i][j] = fmaf(ar[i], br[j], acc[i][j]);
        }
        __syncthreads();
    }

    int gr0 = by * 128, gc0 = bx * 128;
    float sa[8], sb[8];
    #pragma unroll
    for (int i = 0; i < 8; i++) sa[i] = sA[gr0 + trow + i];
    #pragma unroll
    for (int j = 0; j < 8; j++) sb[j] = sB[gc0 + tcol + j];

    #pragma unroll
    for (int i = 0; i < 8; i++) {
        #pragma unroll
        for (int j = 0; j < 8; j += 2) {
            float sq0 = sa[i] + sb[j]     - 2.f * acc[i][j];
            float sq1 = sa[i] + sb[j + 1] - 2.f * acc[i][j + 1];
            float d0 = sqrtf(fmaxf(sq0, 1e-12f));
            float d1 = sqrtf(fmaxf(sq1, 1e-12f));
            unsigned int q0 = min(65535u, __float2uint_rn(d0 * QSCALE));
            unsigned int q1 = min(65535u, __float2uint_rn(d1 * QSCALE));
            ts[trow + i][(tcol + j) >> 1] = q0 | (q1 << 16);
        }
    }
    __syncthreads();

    for (int idx = tid; idx < 128 * 16; idx += 256) {
        int r = idx >> 4, seg = idx & 15;
        uint4 w;
        w.x = ts[r][seg * 4 + 0];
        w.y = ts[r][seg * 4 + 1];
        w.z = ts[r][seg * 4 + 2];
        w.w = ts[r][seg * 4 + 3];
        *(uint4*)&C[(size_t)(gr0 + r) * N + gc0 + seg * 8] = w;
    }
    for (int idx = tid; idx < 128 * 16; idx += 256) {
        int c = idx >> 4, seg = idx & 15;
        uint4 w;
        unsigned int sh = (c & 1) * 16;
        #pragma unroll
        for (int k = 0; k < 4; k++) {
            int r = seg * 8 + k * 2;
            unsigned int lo = (ts[r][c >> 1] >> sh) & 0xFFFFu;
            unsigned int hi = (ts[r + 1][c >> 1] >> sh) & 0xFFFFu;
            ((unsigned int*)&w)[k] = lo | (hi << 16);
        }
        *(uint4*)&Cm[(size_t)(gc0 + c) * N + gr0 + seg * 8] = w;
    }
}

// operand selection shared by LSE/build/sparse kernels
#define LSE_SELECT() \
    const float* base_r = &d_vecs[parity][0][0]; \
    float* base_w = &d_vecs[parity ^ 1][0][0]; \
    const unsigned short* Cq; const float* vin; const float* vold; float* vout; \
    if (which == 0)      { Cq = d_Cxy; vin = base_r + N;     vold = base_r;         vout = base_w;         } \
    else if (which == 1) { Cq = d_Cyx; vin = base_r;         vold = base_r + N;     vout = base_w + N;     } \
    else if (which == 2) { Cq = d_Cxx; vin = base_r + 2 * N; vold = base_r + 2 * N; vout = base_w + 2 * N; } \
    else                 { Cq = d_Cyy; vin = base_r + 3 * N; vold = base_r + 3 * N; vout = base_w + 3 * N; }

#define DEC2(uw, vka, vkb, a0, a1) \
    { float q0 = __uint_as_float(0x4B000000u | ((uw) & 0xFFFFu)); \
      float q1 = __uint_as_float(0x4B000000u | ((uw) >> 16)); \
      a0 = fmaf(q0, nQK, (vka)); \
      a1 = fmaf(q1, nQK, (vkb)); }

// ---------------- two-pass dense LSE (bootstrap; writes d_ref) ----------------
__global__ __launch_bounds__(256, 2) void lse2_kernel(int parity) {
    int row0 = blockIdx.x * ROWS;
    int which = blockIdx.y;
    int tid = threadIdx.x;
    LSE_SELECT();
    float* refp = &d_ref[which][0];

    const float nQK = -QK;
    const float BIG = QK * 8388608.0f;   // exact: QK * 2^23 (decode bias)
    const float4* V4 = (const float4*)vin;

    float vrK[4][8];
    #pragma unroll
    for (int it = 0; it < 4; it++) {
        int base = it * 256 + tid;
        float4 v0 = V4[base * 2];
        float4 v1 = V4[base * 2 + 1];
        vrK[it][0] = fmaf(v0.x, KC, BIG); vrK[it][1] = fmaf(v0.y, KC, BIG);
        vrK[it][2] = fmaf(v0.z, KC, BIG); vrK[it][3] = fmaf(v0.w, KC, BIG);
        vrK[it][4] = fmaf(v1.x, KC, BIG); vrK[it][5] = fmaf(v1.y, KC, BIG);
        vrK[it][6] = fmaf(v1.z, KC, BIG); vrK[it][7] = fmaf(v1.w, KC, BIG);
    }

    const unsigned short* Cb = Cq + (size_t)row0 * N;
    uint4 cur[4], nxt[4], nxt2[4];
    #pragma unroll
    for (int it = 0; it < 4; it++)
        cur[it] = ((const uint4*)Cb)[it * 256 + tid];
    {
        const uint4* Cn = (const uint4*)(Cb + (size_t)N);
        #pragma unroll
        for (int it = 0; it < 4; it++)
            nxt[it] = Cn[it * 256 + tid];
    }

    __shared__ float sm[8];
    __shared__ float ssum[8];
    int w = tid >> 5, lane = tid & 31;

    #pragma unroll 4
    for (int r = 0; r < ROWS; r++) {
        if (r + 2 < ROWS) {
            const uint4* Cn = (const uint4*)(Cb + (size_t)(r + 2) * N);
            #pragma unroll
            for (int it = 0; it < 4; it++) nxt2[it] = Cn[it * 256 + tid];
        }

        float gm[4];
        float m = -CUDART_INF_F;
        #pragma unroll
        for (int it = 0; it < 4; it++) {
            float a0, a1, a2, a3, a4, a5, a6, a7;
            DEC2(cur[it].x, vrK[it][0], vrK[it][1], a0, a1);
            DEC2(cur[it].y, vrK[it][2], vrK[it][3], a2, a3);
            DEC2(cur[it].z, vrK[it][4], vrK[it][5], a4, a5);
            DEC2(cur[it].w, vrK[it][6], vrK[it][7], a6, a7);
            float g = fmaxf(fmaxf(fmaxf(a0, a1), fmaxf(a2, a3)),
                            fmaxf(fmaxf(a4, a5), fmaxf(a6, a7)));
            gm[it] = g;
            m = fmaxf(m, g);
        }
        #pragma unroll
        for (int o = 16; o; o >>= 1) m = fmaxf(m, __shfl_xor_sync(0xffffffffu, m, o));
        if (lane == 0) sm[w] = m;
        __syncthreads();
        float Mx = sm[0];
        #pragma unroll
        for (int i = 1; i < 8; i++) Mx = fmaxf(Mx, sm[i]);

        float thr = Mx - 25.f;
        float s = 0.f;
        #pragma unroll
        for (int it = 0; it < 4; it++) {
            if (__ballot_sync(0xffffffffu, gm[it] > thr)) {
                float a0, a1, a2, a3, a4, a5, a6, a7;
                DEC2(cur[it].x, vrK[it][0], vrK[it][1], a0, a1);
                DEC2(cur[it].y, vrK[it][2], vrK[it][3], a2, a3);
                DEC2(cur[it].z, vrK[it][4], vrK[it][5], a4, a5);
                DEC2(cur[it].w, vrK[it][6], vrK[it][7], a6, a7);
                if (a0 > thr) s += exp2f(a0 - Mx);
                if (a1 > thr) s += exp2f(a1 - Mx);
                if (a2 > thr) s += exp2f(a2 - Mx);
                if (a3 > thr) s += exp2f(a3 - Mx);
                if (a4 > thr) s += exp2f(a4 - Mx);
                if (a5 > thr) s += exp2f(a5 - Mx);
                if (a6 > thr) s += exp2f(a6 - Mx);
                if (a7 > thr) s += exp2f(a7 - Mx);
            }
        }
        #pragma unroll
        for (int o = 16; o; o >>= 1) s += __shfl_xor_sync(0xffffffffu, s, o);
        if (lane == 0) ssum[w] = s;
        __syncthreads();

        if (tid == 0) {
            float S = ssum[0];
            #pragma unroll
            for (int i = 1; i < 8; i++) S += ssum[i];
            float lse2 = Mx + log2f(S);
            vout[row0 + r] = 0.5f * (vold[row0 + r] + EPSLOGN - EPSLN2 * lse2);
            refp[row0 + r] = lse2;
        }

        #pragma unroll
        for (int it = 0; it < 4; it++) { cur[it] = nxt[it]; nxt[it] = nxt2[it]; }
    }
}

// ---------------- sparse list build (one warp per row, deterministic) -------
// Selects entries with a = v*KC - q*QK > ref - MARGIN, compacted in column
// order via warp ballot. Entry = col | (q << 16).
__global__ __launch_bounds__(256) void build_kernel(int parity) {
    int which = blockIdx.y;
    int tid = threadIdx.x;
    LSE_SELECT();
    (void)vold; (void)vout; (void)base_w;
    const float* refp = &d_ref[which][0];
    const float nQK = -QK;
    const float BIG = QK * 8388608.0f;

    __shared__ float vK[N];
    {
        const float4* V4 = (const float4*)vin;
        for (int g = tid; g < N / 4; g += 256) {
            float4 v = V4[g];
            vK[4 * g + 0] = fmaf(v.x, KC, BIG);
            vK[4 * g + 1] = fmaf(v.y, KC, BIG);
            vK[4 * g + 2] = fmaf(v.z, KC, BIG);
            vK[4 * g + 3] = fmaf(v.w, KC, BIG);
        }
    }
    __syncthreads();

    int w = tid >> 5, lane = tid & 31;
    int row = blockIdx.x * 8 + w;
    const uint2* Crow = (const uint2*)(Cq + (size_t)row * N);   // 4 ushorts each
    unsigned int* out = &d_sparse[which][row][0];
    float sel = refp[row] - MARGIN;
    int cnt = 0;

    for (int t = 0; t < N / 128; t++) {
        uint2 u = Crow[t * 32 + lane];
        unsigned int qs[4] = { u.x & 0xFFFFu, u.x >> 16, u.y & 0xFFFFu, u.y >> 16 };
        #pragma unroll
        for (int e = 0; e < 4; e++) {
            int col = t * 128 + lane * 4 + e;
            unsigned int q = qs[e];
            float a = fmaf(__uint_as_float(0x4B000000u | q), nQK, vK[col]);
            bool pred = a > sel;
            unsigned int mask = __ballot_sync(0xffffffffu, pred);
            int pos = cnt + __popc(mask & ((1u << lane) - 1u));
            if (pred && pos < CAP) out[pos] = (unsigned int)col | (q << 16);
            cnt += __popc(mask);
        }
    }
    if (lane == 0) d_scount[which][row] = min(cnt, CAP);
}

// ---------------- sparse ref-based LSE iteration (gather, no smem) ----------
// One warp per row (4 rows serially). v[col] gathered directly from the 32KB
// vector table (L1/L2 resident). No block barriers, no smem stage.
// mode=0: damped update + ref refresh; mode=1: extrapolation.
__global__ __launch_bounds__(256) void sparse_kernel(int parity, int mode) {
    int which = blockIdx.y;
    int tid = threadIdx.x;
    LSE_SELECT();
    if (mode) vout = &d_evec[which][0];
    float* refp = &d_ref[which][0];
    const float nQK = -QK;
    const float BIG = QK * 8388608.0f;
    (void)Cq;

    int w = tid >> 5, lane = tid & 31;
    int row0 = blockIdx.x * 32 + w * 4;

    #pragma unroll 1
    for (int r = 0; r < 4; r++) {
        int row = row0 + r;
        int cnt = d_scount[which][row];
        float R = refp[row];
        float thr = R - 30.f;
        float s = 0.f;
        const unsigned int* sp = &d_sparse[which][row][0];
        for (int t = lane; t < cnt; t += 32) {
            unsigned int e = sp[t];
            float v = vin[e & 0xFFFFu];                 // gather, L1/L2 hit
            float a = fmaf(__uint_as_float(0x4B000000u | (e >> 16)), nQK,
                           fmaf(v, KC, BIG));
            if (a > thr) s += exp2f(a - R);
        }
        #pragma unroll
        for (int o = 16; o; o >>= 1) s += __shfl_xor_sync(0xffffffffu, s, o);

        if (lane == 0) {
            float lse2 = R + log2f(s);
            float val;
            if (mode) val = EPSLOGN - EPSLN2 * lse2;
            else      val = 0.5f * (vold[row] + EPSLOGN - EPSLN2 * lse2);
            vout[row] = val;
            if (!mode) refp[row] = lse2;
        }
    }
}

// ---------------- final scalar reduction ----------------
__global__ void final_kernel(float* out) {
    __shared__ double sh[32];
    double acc = 0.0;
    for (int i = threadIdx.x; i < N; i += 1024) {
        acc += (double)d_evec[0][i] - (double)d_evec[2][i]
             + (double)d_evec[1][i] - (double)d_evec[3][i];
    }
    #pragma unroll
    for (int o = 16; o; o >>= 1) acc += __shfl_down_sync(0xffffffffu, acc, o);
    int w = threadIdx.x >> 5, lane = threadIdx.x & 31;
    if (lane == 0) sh[w] = acc;
    __syncthreads();
    if (threadIdx.x < 32) {
        double a = sh[threadIdx.x];
        #pragma unroll
        for (int o = 16; o; o >>= 1) a += __shfl_down_sync(0xffffffffu, a, o);
        if (threadIdx.x == 0) out[0] = (float)(a / (double)N);
    }
}

// ---------------- launch ----------------
extern "C" void kernel_launch(void* const* d_in, const int* in_sizes, int n_in,
                              void* d_out, int out_size) {
    (void)in_sizes; (void)n_in; (void)out_size;
    const float* x  = (const float*)d_in[0];   // xt
    const float* pz = (const float*)d_in[1];   // xs

    rownorm_kernel<<<dim3(N / 8, 2), 256>>>(x, pz);
    init_kernel<<<(2 * 4 * N + 255) / 256, 256>>>();

    dim3 gg(64, 64);
    gemm_dist_kernel<<<gg, 256>>>(x, pz, 0);
    gemm_dist_kernel<<<gg, 256>>>(x, pz, 1);
    gemm_dist_kernel<<<gg, 256>>>(x, pz, 2);

    for (int it = 0; it < BOOT; ++it)
        lse2_kernel<<<dim3(NBLK, 4), 256>>>(it & 1);     // dense two-pass, writes refs

    build_kernel<<<dim3(N / 8, 4), 256>>>(BOOT & 1);     // sparse candidate lists

    for (int it = BOOT; it < 50; ++it)
        sparse_kernel<<<dim3(N / 32, 4), 256>>>(it & 1, 0);

    sparse_kernel<<<dim3(N / 32, 4), 256>>>(0, 1);       // extrapolation (final vecs in slot 0)
    final_kernel<<<1, 1024>>>((float*)d_out);
}